// round 1
// baseline (speedup 1.0000x reference)
#include <cuda_runtime.h>

#define N_NODES 50000
#define N_EDGES 800000
#define D_IN    256
#define D_HID   256
#define D_OUT   128

// ---------------- scratch (static device globals; no allocation) -------------
__device__ float g_H1[(size_t)N_NODES * D_IN];    // Y @ W1
__device__ float g_H2[(size_t)N_NODES * D_HID];   // relu(spmm(H1))
__device__ float g_H3[(size_t)N_NODES * D_OUT];   // H2 @ W2
__device__ int   g_rowptr[N_NODES + 1];
__device__ int   g_cursor[N_NODES];
__device__ int   g_cols[N_EDGES];
__device__ float g_vals[N_EDGES];

// ---------------- CSR construction ------------------------------------------
__global__ void k_zero_int(int* p, int n) {
    int i = blockIdx.x * blockDim.x + threadIdx.x;
    if (i < n) p[i] = 0;
}

__global__ void k_hist(const int* __restrict__ row, int E) {
    int i = blockIdx.x * blockDim.x + threadIdx.x;
    if (i < E) atomicAdd(&g_rowptr[row[i] + 1], 1);
}

// single-block inclusive scan over g_rowptr[0..n-1]  (n = N_NODES+1, g_rowptr[0]==0)
__global__ void k_scan(int n) {
    const int T = 1024;
    const int CHUNK = (N_NODES + 1 + T - 1) / T;  // 49
    __shared__ int ssum[T];
    int tid = threadIdx.x;
    int base = tid * CHUNK;
    int s = 0;
    for (int i = 0; i < CHUNK; i++) {
        int idx = base + i;
        if (idx < n) s += g_rowptr[idx];
    }
    ssum[tid] = s;
    __syncthreads();
    // Hillis-Steele inclusive scan over 1024 partials
    for (int off = 1; off < T; off <<= 1) {
        int v = (tid >= off) ? ssum[tid - off] : 0;
        __syncthreads();
        ssum[tid] += v;
        __syncthreads();
    }
    int prefix = (tid > 0) ? ssum[tid - 1] : 0;
    for (int i = 0; i < CHUNK; i++) {
        int idx = base + i;
        if (idx < n) {
            prefix += g_rowptr[idx];
            g_rowptr[idx] = prefix;
        }
    }
}

__global__ void k_copy_cursor(int n) {
    int i = blockIdx.x * blockDim.x + threadIdx.x;
    if (i < n) g_cursor[i] = g_rowptr[i];
}

__global__ void k_scatter(const int* __restrict__ row, const int* __restrict__ col,
                          const float* __restrict__ val, int E) {
    int i = blockIdx.x * blockDim.x + threadIdx.x;
    if (i < E) {
        int r = row[i];
        int p = atomicAdd(&g_cursor[r], 1);
        g_cols[p] = col[i];
        g_vals[p] = val[i];
    }
}

// ---------------- dense GEMM: C[M,N] = A[M,K] @ B[K,N] -----------------------
// BM=BN=128, BK=16, 256 threads, 8x8 register micro-tile.
__global__ __launch_bounds__(256)
void k_gemm(const float* __restrict__ A, const float* __restrict__ B,
            float* __restrict__ C, int M, int N, int K) {
    __shared__ __align__(16) float As[16][132];  // k-major: As[k][m]
    __shared__ __align__(16) float Bs[16][132];  // Bs[k][n]

    int tid = threadIdx.x;
    int tr = tid >> 4;        // 0..15
    int tc = tid & 15;        // 0..15
    int rowBase = blockIdx.y * 128;
    int colBase = blockIdx.x * 128;

    float acc[8][8];
#pragma unroll
    for (int i = 0; i < 8; i++)
#pragma unroll
        for (int j = 0; j < 8; j++) acc[i][j] = 0.f;

    for (int k0 = 0; k0 < K; k0 += 16) {
        // load A tile 128 rows x 16 k, store transposed
#pragma unroll
        for (int i = 0; i < 8; i++) {
            int idx = tid + i * 256;
            int r = idx >> 4;      // 0..127
            int c = idx & 15;      // 0..15
            int gr = rowBase + r;
            float v = (gr < M) ? A[(size_t)gr * K + k0 + c] : 0.f;
            As[c][r] = v;
        }
        // load B tile 16 k x 128 n
#pragma unroll
        for (int i = 0; i < 8; i++) {
            int idx = tid + i * 256;
            int r = idx >> 7;      // 0..15
            int c = idx & 127;     // 0..127
            Bs[r][c] = B[(size_t)(k0 + r) * N + colBase + c];
        }
        __syncthreads();

#pragma unroll
        for (int kk = 0; kk < 16; kk++) {
            float a[8], b[8];
            *(float4*)&a[0] = *(const float4*)&As[kk][tr * 8];
            *(float4*)&a[4] = *(const float4*)&As[kk][tr * 8 + 4];
            *(float4*)&b[0] = *(const float4*)&Bs[kk][tc * 8];
            *(float4*)&b[4] = *(const float4*)&Bs[kk][tc * 8 + 4];
#pragma unroll
            for (int i = 0; i < 8; i++)
#pragma unroll
                for (int j = 0; j < 8; j++)
                    acc[i][j] += a[i] * b[j];
        }
        __syncthreads();
    }

#pragma unroll
    for (int i = 0; i < 8; i++) {
        int gr = rowBase + tr * 8 + i;
        if (gr < M) {
            float4 v0 = make_float4(acc[i][0], acc[i][1], acc[i][2], acc[i][3]);
            float4 v1 = make_float4(acc[i][4], acc[i][5], acc[i][6], acc[i][7]);
            *(float4*)&C[(size_t)gr * N + colBase + tc * 8]     = v0;
            *(float4*)&C[(size_t)gr * N + colBase + tc * 8 + 4] = v1;
        }
    }
}

// ---------------- CSR SpMM: Y[r,f] = sum_e val[e] * X[col[e], f] -------------
// one block per row, F threads (F = 256 or 128). Optional fused ReLU.
template <int F, bool RELU>
__global__ void k_spmm(const float* __restrict__ X, float* __restrict__ Yout) {
    int r = blockIdx.x;
    int f = threadIdx.x;
    int start = g_rowptr[r];
    int end   = g_rowptr[r + 1];
    float acc = 0.f;
    for (int e = start; e < end; e++) {
        int   c = __ldg(&g_cols[e]);
        float v = __ldg(&g_vals[e]);
        acc += v * __ldg(&X[(size_t)c * F + f]);
    }
    if (RELU) acc = fmaxf(acc, 0.f);
    Yout[(size_t)r * F + f] = acc;
}

// ---------------- launch ------------------------------------------------------
extern "C" void kernel_launch(void* const* d_in, const int* in_sizes, int n_in,
                              void* d_out, int out_size) {
    const float* Y        = (const float*)d_in[0];
    const int*   edge_row = (const int*)d_in[1];
    const int*   edge_col = (const int*)d_in[2];
    const float* edge_val = (const float*)d_in[3];
    const float* W1       = (const float*)d_in[4];
    const float* W2       = (const float*)d_in[5];
    float*       out      = (float*)d_out;

    float *pH1, *pH2, *pH3;
    int   *pRowptr, *pCursor;
    cudaGetSymbolAddress((void**)&pH1, g_H1);
    cudaGetSymbolAddress((void**)&pH2, g_H2);
    cudaGetSymbolAddress((void**)&pH3, g_H3);
    cudaGetSymbolAddress((void**)&pRowptr, g_rowptr);
    cudaGetSymbolAddress((void**)&pCursor, g_cursor);

    // ---- CSR build (counting sort by row) ----
    k_zero_int<<<(N_NODES + 1 + 255) / 256, 256>>>(pRowptr, N_NODES + 1);
    k_hist<<<(N_EDGES + 255) / 256, 256>>>(edge_row, N_EDGES);
    k_scan<<<1, 1024>>>(N_NODES + 1);
    k_copy_cursor<<<(N_NODES + 255) / 256, 256>>>(N_NODES);
    k_scatter<<<(N_EDGES + 255) / 256, 256>>>(edge_row, edge_col, edge_val, N_EDGES);

    // ---- layer 1: H1 = Y @ W1 ----
    {
        dim3 grid(D_HID / 128, (N_NODES + 127) / 128);
        k_gemm<<<grid, 256>>>(Y, W1, pH1, N_NODES, D_HID, D_IN);
    }
    // ---- H2 = relu(spmm(H1)) ----
    k_spmm<D_HID, true><<<N_NODES, D_HID>>>(pH1, pH2);

    // ---- layer 2: H3 = H2 @ W2 ----
    {
        dim3 grid(D_OUT / 128, (N_NODES + 127) / 128);
        k_gemm<<<grid, 256>>>(pH2, W2, pH3, N_NODES, D_OUT, D_HID);
    }
    // ---- out = spmm(H3) ----
    k_spmm<D_OUT, false><<<N_NODES, D_OUT>>>(pH3, out);
}

// round 2
// speedup vs baseline: 1.1314x; 1.1314x over previous
#include <cuda_runtime.h>

#define N_NODES 50000
#define N_EDGES 800000
#define D_IN    256
#define D_HID   256
#define D_OUT   128

// ---------------- scratch (static device globals; no allocation) -------------
__device__ float g_H1[(size_t)N_NODES * D_IN];    // Y @ W1
__device__ float g_H2[(size_t)N_NODES * D_HID];   // relu(spmm(H1))
__device__ float g_H3[(size_t)N_NODES * D_OUT];   // H2 @ W2
__device__ int   g_rowptr[N_NODES + 1];
__device__ int   g_cursor[N_NODES];
__device__ int   g_cols[N_EDGES];
__device__ float g_vals[N_EDGES];

// packed f32x2 FMA: d = a*b + c per 32-bit half (exact fp32, 2x FMA pipe tput)
__device__ __forceinline__ unsigned long long fma2(unsigned long long a,
                                                   unsigned long long b,
                                                   unsigned long long c) {
    unsigned long long d;
    asm("fma.rn.f32x2 %0, %1, %2, %3;" : "=l"(d) : "l"(a), "l"(b), "l"(c));
    return d;
}

// ---------------- CSR construction ------------------------------------------
__global__ void k_zero_int(int* p, int n) {
    int i = blockIdx.x * blockDim.x + threadIdx.x;
    if (i < n) p[i] = 0;
}

__global__ void k_hist(const int* __restrict__ row, int E) {
    int i = blockIdx.x * blockDim.x + threadIdx.x;
    if (i < E) atomicAdd(&g_rowptr[row[i] + 1], 1);
}

// single-block inclusive scan over g_rowptr[0..n-1]
__global__ void k_scan(int n) {
    const int T = 1024;
    const int CHUNK = (N_NODES + 1 + T - 1) / T;
    __shared__ int ssum[T];
    int tid = threadIdx.x;
    int base = tid * CHUNK;
    int s = 0;
    for (int i = 0; i < CHUNK; i++) {
        int idx = base + i;
        if (idx < n) s += g_rowptr[idx];
    }
    ssum[tid] = s;
    __syncthreads();
    for (int off = 1; off < T; off <<= 1) {
        int v = (tid >= off) ? ssum[tid - off] : 0;
        __syncthreads();
        ssum[tid] += v;
        __syncthreads();
    }
    int prefix = (tid > 0) ? ssum[tid - 1] : 0;
    for (int i = 0; i < CHUNK; i++) {
        int idx = base + i;
        if (idx < n) {
            prefix += g_rowptr[idx];
            g_rowptr[idx] = prefix;
        }
    }
}

__global__ void k_copy_cursor(int n) {
    int i = blockIdx.x * blockDim.x + threadIdx.x;
    if (i < n) g_cursor[i] = g_rowptr[i];
}

__global__ void k_scatter(const int* __restrict__ row, const int* __restrict__ col,
                          const float* __restrict__ val, int E) {
    int i = blockIdx.x * blockDim.x + threadIdx.x;
    if (i < E) {
        int r = row[i];
        int p = atomicAdd(&g_cursor[r], 1);
        g_cols[p] = col[i];
        g_vals[p] = val[i];
    }
}

// ---------------- dense GEMM: C[M,N] = A[M,K] @ B[K,N] -----------------------
// BM=BN=128, BK=16, 256 threads, 8x8 micro-tile computed with fma.rn.f32x2.
// A tile is stored DUPLICATED in smem (each value twice, adjacent) so that
// {a[i],a[i]} broadcast pairs are direct 64-bit lane-pairs; B pairs naturally.
__global__ __launch_bounds__(256)
void k_gemm(const float* __restrict__ A, const float* __restrict__ B,
            float* __restrict__ C, int M, int N, int K) {
    __shared__ __align__(16) float As[16][260];  // As[k][2m]=As[k][2m+1]=A[m][k]
    __shared__ __align__(16) float Bs[16][132];  // Bs[k][n]

    int tid = threadIdx.x;
    int tr = tid >> 4;        // 0..15
    int tc = tid & 15;        // 0..15
    int rowBase = blockIdx.y * 128;
    int colBase = blockIdx.x * 128;

    unsigned long long acc2[8][4];  // [row i][col-pair j2]
#pragma unroll
    for (int i = 0; i < 8; i++)
#pragma unroll
        for (int j = 0; j < 4; j++) acc2[i][j] = 0ull;

    for (int k0 = 0; k0 < K; k0 += 16) {
        // load A tile 128 rows x 16 k, duplicated
#pragma unroll
        for (int i = 0; i < 8; i++) {
            int idx = tid + i * 256;
            int r = idx >> 4;      // 0..127
            int c = idx & 15;      // 0..15
            int gr = rowBase + r;
            float v = (gr < M) ? A[(size_t)gr * K + k0 + c] : 0.f;
            As[c][2 * r]     = v;
            As[c][2 * r + 1] = v;
        }
        // load B tile 16 k x 128 n
#pragma unroll
        for (int i = 0; i < 8; i++) {
            int idx = tid + i * 256;
            int r = idx >> 7;      // 0..15
            int c = idx & 127;     // 0..127
            Bs[r][c] = B[(size_t)(k0 + r) * N + colBase + c];
        }
        __syncthreads();

#pragma unroll
        for (int kk = 0; kk < 16; kk++) {
            union { float4 f[4]; unsigned long long u[8]; } ua;  // {a_i,a_i} pairs
            union { float4 f[2]; unsigned long long u[4]; } ub;  // {b_2j,b_2j+1}
            ua.f[0] = *(const float4*)&As[kk][tr * 16];
            ua.f[1] = *(const float4*)&As[kk][tr * 16 + 4];
            ua.f[2] = *(const float4*)&As[kk][tr * 16 + 8];
            ua.f[3] = *(const float4*)&As[kk][tr * 16 + 12];
            ub.f[0] = *(const float4*)&Bs[kk][tc * 8];
            ub.f[1] = *(const float4*)&Bs[kk][tc * 8 + 4];
#pragma unroll
            for (int i = 0; i < 8; i++)
#pragma unroll
                for (int j = 0; j < 4; j++)
                    acc2[i][j] = fma2(ua.u[i], ub.u[j], acc2[i][j]);
        }
        __syncthreads();
    }

#pragma unroll
    for (int i = 0; i < 8; i++) {
        int gr = rowBase + tr * 8 + i;
        if (gr < M) {
            *(float4*)&C[(size_t)gr * N + colBase + tc * 8] =
                *(float4*)&acc2[i][0];
            *(float4*)&C[(size_t)gr * N + colBase + tc * 8 + 4] =
                *(float4*)&acc2[i][2];
        }
    }
}

// ---------------- CSR SpMM: Y[r,f] = sum_e val[e] * X[col[e], f] -------------
// float4 per thread; F/4 threads per row; ROWS_PER_BLK rows per 256-thread CTA.
template <int F, bool RELU>
__global__ void k_spmm4(const float* __restrict__ X, float* __restrict__ Yout) {
    const int TPR = F / 4;
    int r = blockIdx.x * blockDim.y + threadIdx.y;
    if (r >= N_NODES) return;
    int f4 = threadIdx.x;   // 0..TPR-1
    int start = g_rowptr[r];
    int end   = g_rowptr[r + 1];
    float4 acc = make_float4(0.f, 0.f, 0.f, 0.f);
    for (int e = start; e < end; e++) {
        int   c = __ldg(&g_cols[e]);
        float v = __ldg(&g_vals[e]);
        float4 x = *(const float4*)&X[(size_t)c * F + f4 * 4];
        acc.x += v * x.x;
        acc.y += v * x.y;
        acc.z += v * x.z;
        acc.w += v * x.w;
    }
    if (RELU) {
        acc.x = fmaxf(acc.x, 0.f);
        acc.y = fmaxf(acc.y, 0.f);
        acc.z = fmaxf(acc.z, 0.f);
        acc.w = fmaxf(acc.w, 0.f);
    }
    *(float4*)&Yout[(size_t)r * F + f4 * 4] = acc;
}

// ---------------- launch ------------------------------------------------------
extern "C" void kernel_launch(void* const* d_in, const int* in_sizes, int n_in,
                              void* d_out, int out_size) {
    const float* Y        = (const float*)d_in[0];
    const int*   edge_row = (const int*)d_in[1];
    const int*   edge_col = (const int*)d_in[2];
    const float* edge_val = (const float*)d_in[3];
    const float* W1       = (const float*)d_in[4];
    const float* W2       = (const float*)d_in[5];
    float*       out      = (float*)d_out;

    float *pH1, *pH2, *pH3;
    int   *pRowptr, *pCursor;
    cudaGetSymbolAddress((void**)&pH1, g_H1);
    cudaGetSymbolAddress((void**)&pH2, g_H2);
    cudaGetSymbolAddress((void**)&pH3, g_H3);
    cudaGetSymbolAddress((void**)&pRowptr, g_rowptr);
    cudaGetSymbolAddress((void**)&pCursor, g_cursor);

    // ---- CSR build (counting sort by row) ----
    k_zero_int<<<(N_NODES + 1 + 255) / 256, 256>>>(pRowptr, N_NODES + 1);
    k_hist<<<(N_EDGES + 255) / 256, 256>>>(edge_row, N_EDGES);
    k_scan<<<1, 1024>>>(N_NODES + 1);
    k_copy_cursor<<<(N_NODES + 255) / 256, 256>>>(N_NODES);
    k_scatter<<<(N_EDGES + 255) / 256, 256>>>(edge_row, edge_col, edge_val, N_EDGES);

    // ---- layer 1: H1 = Y @ W1 ----
    {
        dim3 grid(D_HID / 128, (N_NODES + 127) / 128);
        k_gemm<<<grid, 256>>>(Y, W1, pH1, N_NODES, D_HID, D_IN);
    }
    // ---- H2 = relu(spmm(H1)) ----
    {
        dim3 blk(D_HID / 4, 4);   // 64 x 4 = 256 threads
        k_spmm4<D_HID, true><<<(N_NODES + 3) / 4, blk>>>(pH1, pH2);
    }
    // ---- layer 2: H3 = H2 @ W2 ----
    {
        dim3 grid(D_OUT / 128, (N_NODES + 127) / 128);
        k_gemm<<<grid, 256>>>(pH2, W2, pH3, N_NODES, D_OUT, D_HID);
    }
    // ---- out = spmm(H3) ----
    {
        dim3 blk(D_OUT / 4, 8);   // 32 x 8 = 256 threads
        k_spmm4<D_OUT, false><<<(N_NODES + 7) / 8, blk>>>(pH3, out);
    }
}

// round 4
// speedup vs baseline: 2.0501x; 1.8120x over previous
#include <cuda_runtime.h>
#include <cuda_bf16.h>
#include <cstdint>

#define N_NODES 50000
#define N_EDGES 800000
#define D_IN    256
#define D_HID   256
#define D_OUT   128

// ---------------- scratch (static device globals; no allocation) -------------
__device__ float g_H1[(size_t)N_NODES * D_HID];   // Y @ W1
__device__ float g_H2[(size_t)N_NODES * D_HID];   // relu(spmm(H1))
__device__ float g_H3[(size_t)N_NODES * D_OUT];   // H2 @ W2
__device__ __nv_bfloat16 g_W1Th[D_HID * D_IN];    // W1^T hi  [N=256][K=256]
__device__ __nv_bfloat16 g_W1Tl[D_HID * D_IN];    // W1^T lo
__device__ __nv_bfloat16 g_W2Th[D_OUT * D_HID];   // W2^T hi  [N=128][K=256]
__device__ __nv_bfloat16 g_W2Tl[D_OUT * D_HID];   // W2^T lo
__device__ int   g_rowptr[N_NODES + 1];
__device__ int   g_cursor[N_NODES];
__device__ int   g_cols[N_EDGES];
__device__ float g_vals[N_EDGES];

// ---------------- CSR construction ------------------------------------------
__global__ void k_zero_int(int* p, int n) {
    int i = blockIdx.x * blockDim.x + threadIdx.x;
    if (i < n) p[i] = 0;
}

__global__ void k_hist(const int* __restrict__ row, int E) {
    int i = blockIdx.x * blockDim.x + threadIdx.x;
    if (i < E) atomicAdd(&g_rowptr[row[i] + 1], 1);
}

// single-block inclusive scan; also writes g_cursor
__global__ void k_scan(int n) {
    const int T = 1024;
    const int CHUNK = (N_NODES + 1 + T - 1) / T;
    __shared__ int ssum[T];
    int tid = threadIdx.x;
    int base = tid * CHUNK;
    int s = 0;
    for (int i = 0; i < CHUNK; i++) {
        int idx = base + i;
        if (idx < n) s += g_rowptr[idx];
    }
    ssum[tid] = s;
    __syncthreads();
    for (int off = 1; off < T; off <<= 1) {
        int v = (tid >= off) ? ssum[tid - off] : 0;
        __syncthreads();
        ssum[tid] += v;
        __syncthreads();
    }
    int prefix = (tid > 0) ? ssum[tid - 1] : 0;
    for (int i = 0; i < CHUNK; i++) {
        int idx = base + i;
        if (idx < n) {
            prefix += g_rowptr[idx];
            g_rowptr[idx] = prefix;
            if (idx < N_NODES) g_cursor[idx] = prefix;
        }
    }
}

__global__ void k_scatter(const int* __restrict__ row, const int* __restrict__ col,
                          const float* __restrict__ val, int E) {
    int i = blockIdx.x * blockDim.x + threadIdx.x;
    if (i < E) {
        int r = row[i];
        int p = atomicAdd(&g_cursor[r], 1);
        g_cols[p] = col[i];
        g_vals[p] = val[i];
    }
}

// ---------------- W transpose + bf16 split -----------------------------------
// Dh/Dl[c*R + r] = split(S[r*C + c]); output layout [N=C][K=R]
__global__ void k_tsplit(const float* __restrict__ S, __nv_bfloat16* __restrict__ Dh,
                         __nv_bfloat16* __restrict__ Dl, int R, int C) {
    int i = blockIdx.x * blockDim.x + threadIdx.x;
    if (i < R * C) {
        int r = i / C, c = i % C;
        float v = S[i];
        __nv_bfloat16 h = __float2bfloat16(v);
        float res = v - __bfloat162float(h);
        Dh[(size_t)c * R + r] = h;
        Dl[(size_t)c * R + r] = __float2bfloat16(res);
    }
}

// ---------------- HMMA GEMM: C[M,N] = A[M,256] @ BT[N,256]^T -----------------
// 3-term bf16 split: Ah*Bh + Ah*Bl + Al*Bh, fp32 accum.
// A: f32, split on the fly. B: pre-split bf16 [N][K].
// CTA 128x128, BK=32, 8 warps (warp tile 64x32), mma.sync.m16n8k16.
__device__ __forceinline__ void mma_bf16(float* c, const uint32_t* a, const uint32_t* b) {
    asm("mma.sync.aligned.m16n8k16.row.col.f32.bf16.bf16.f32 "
        "{%0,%1,%2,%3}, {%4,%5,%6,%7}, {%8,%9}, {%0,%1,%2,%3};"
        : "+f"(c[0]), "+f"(c[1]), "+f"(c[2]), "+f"(c[3])
        : "r"(a[0]), "r"(a[1]), "r"(a[2]), "r"(a[3]), "r"(b[0]), "r"(b[1]));
}

__global__ __launch_bounds__(256, 2)
void k_gemm_mma(const float* __restrict__ A,
                const __nv_bfloat16* __restrict__ Bh,
                const __nv_bfloat16* __restrict__ Bl,
                float* __restrict__ C, int M, int N)
{
    const int K = 256;
    const int SP = 40;  // smem row stride in bf16 (80 B = 20 banks, conflict-free)
    __shared__ __nv_bfloat16 sAh[128][SP];
    __shared__ __nv_bfloat16 sAl[128][SP];
    __shared__ __nv_bfloat16 sBh[128][SP];
    __shared__ __nv_bfloat16 sBl[128][SP];

    int tid = threadIdx.x;
    int lane = tid & 31, wid = tid >> 5;
    int rowBase = blockIdx.y * 128, colBase = blockIdx.x * 128;
    int wm = (wid >> 2) * 64;   // warp m offset (0 or 64)
    int wn = (wid & 3) * 32;    // warp n offset (0,32,64,96)

    float acc[4][4][4];
#pragma unroll
    for (int mi = 0; mi < 4; mi++)
#pragma unroll
        for (int ni = 0; ni < 4; ni++)
#pragma unroll
            for (int q = 0; q < 4; q++) acc[mi][ni][q] = 0.f;

    for (int k0 = 0; k0 < K; k0 += 32) {
        // ---- A tile: load f32, split to bf16 hi/lo. 128 rows x 32 cols.
        // 1024 chunks of 4 floats; 4 per thread.
#pragma unroll
        for (int it = 0; it < 4; it++) {
            int ch = tid + it * 256;
            int r = ch >> 3, c = ch & 7;     // c*4 floats within the 32-col slab
            int gr = rowBase + r;
            float4 f = make_float4(0.f, 0.f, 0.f, 0.f);
            if (gr < M) f = *(const float4*)(A + (size_t)gr * K + k0 + c * 4);
            __nv_bfloat162 h01 = __floats2bfloat162_rn(f.x, f.y);
            __nv_bfloat162 h23 = __floats2bfloat162_rn(f.z, f.w);
            float2 g01 = __bfloat1622float2(h01);
            float2 g23 = __bfloat1622float2(h23);
            __nv_bfloat162 l01 = __floats2bfloat162_rn(f.x - g01.x, f.y - g01.y);
            __nv_bfloat162 l23 = __floats2bfloat162_rn(f.z - g23.x, f.w - g23.y);
            uint2 uh, ul;
            uh.x = *(uint32_t*)&h01; uh.y = *(uint32_t*)&h23;
            ul.x = *(uint32_t*)&l01; ul.y = *(uint32_t*)&l23;
            *(uint2*)&sAh[r][c * 4] = uh;
            *(uint2*)&sAl[r][c * 4] = ul;
        }
        // ---- B tile: copy pre-split bf16. 128 n-rows x 32 k. 512 chunks of 16B.
#pragma unroll
        for (int it = 0; it < 2; it++) {
            int ch = tid + it * 256;
            int r = ch >> 2, c = ch & 3;     // c*8 bf16
            int gc = colBase + r;            // always < N for our shapes
            uint4 vh = *(const uint4*)(Bh + (size_t)gc * K + k0 + c * 8);
            uint4 vl = *(const uint4*)(Bl + (size_t)gc * K + k0 + c * 8);
            *(uint4*)&sBh[r][c * 8] = vh;
            *(uint4*)&sBl[r][c * 8] = vl;
        }
        __syncthreads();

#pragma unroll
        for (int ks = 0; ks < 2; ks++) {
            int kc = ks * 16 + (lane & 3) * 2;
            int ar = lane >> 2;
            uint32_t ah[4][4], al[4][4], bh[4][2], bl[4][2];
#pragma unroll
            for (int mi = 0; mi < 4; mi++) {
                int rr = wm + mi * 16 + ar;
                ah[mi][0] = *(const uint32_t*)&sAh[rr][kc];
                ah[mi][1] = *(const uint32_t*)&sAh[rr + 8][kc];
                ah[mi][2] = *(const uint32_t*)&sAh[rr][kc + 8];
                ah[mi][3] = *(const uint32_t*)&sAh[rr + 8][kc + 8];
                al[mi][0] = *(const uint32_t*)&sAl[rr][kc];
                al[mi][1] = *(const uint32_t*)&sAl[rr + 8][kc];
                al[mi][2] = *(const uint32_t*)&sAl[rr][kc + 8];
                al[mi][3] = *(const uint32_t*)&sAl[rr + 8][kc + 8];
            }
#pragma unroll
            for (int ni = 0; ni < 4; ni++) {
                int nr = wn + ni * 8 + ar;
                bh[ni][0] = *(const uint32_t*)&sBh[nr][kc];
                bh[ni][1] = *(const uint32_t*)&sBh[nr][kc + 8];
                bl[ni][0] = *(const uint32_t*)&sBl[nr][kc];
                bl[ni][1] = *(const uint32_t*)&sBl[nr][kc + 8];
            }
#pragma unroll
            for (int mi = 0; mi < 4; mi++)
#pragma unroll
                for (int ni = 0; ni < 4; ni++) {
                    mma_bf16(acc[mi][ni], ah[mi], bh[ni]);
                    mma_bf16(acc[mi][ni], ah[mi], bl[ni]);
                    mma_bf16(acc[mi][ni], al[mi], bh[ni]);
                }
        }
        __syncthreads();
    }

    // ---- epilogue: c0,c1 -> (r, 2c), c2,c3 -> (r+8, 2c)
#pragma unroll
    for (int mi = 0; mi < 4; mi++) {
        int rr = rowBase + wm + mi * 16 + (lane >> 2);
#pragma unroll
        for (int ni = 0; ni < 4; ni++) {
            int cc = colBase + wn + ni * 8 + (lane & 3) * 2;
            if (rr < M)
                *(float2*)&C[(size_t)rr * N + cc] =
                    make_float2(acc[mi][ni][0], acc[mi][ni][1]);
            if (rr + 8 < M)
                *(float2*)&C[(size_t)(rr + 8) * N + cc] =
                    make_float2(acc[mi][ni][2], acc[mi][ni][3]);
        }
    }
}

// ---------------- CSR SpMM: Y[r,f] = sum_e val[e] * X[col[e], f] -------------
template <int F, bool RELU>
__global__ void k_spmm4(const float* __restrict__ X, float* __restrict__ Yout) {
    int r = blockIdx.x * blockDim.y + threadIdx.y;
    if (r >= N_NODES) return;
    int f4 = threadIdx.x;
    int start = g_rowptr[r];
    int end   = g_rowptr[r + 1];
    float4 acc = make_float4(0.f, 0.f, 0.f, 0.f);
    for (int e = start; e < end; e++) {
        int   c = __ldg(&g_cols[e]);
        float v = __ldg(&g_vals[e]);
        float4 x = *(const float4*)&X[(size_t)c * F + f4 * 4];
        acc.x += v * x.x;
        acc.y += v * x.y;
        acc.z += v * x.z;
        acc.w += v * x.w;
    }
    if (RELU) {
        acc.x = fmaxf(acc.x, 0.f);
        acc.y = fmaxf(acc.y, 0.f);
        acc.z = fmaxf(acc.z, 0.f);
        acc.w = fmaxf(acc.w, 0.f);
    }
    *(float4*)&Yout[(size_t)r * F + f4 * 4] = acc;
}

// ---------------- launch ------------------------------------------------------
extern "C" void kernel_launch(void* const* d_in, const int* in_sizes, int n_in,
                              void* d_out, int out_size) {
    const float* Y        = (const float*)d_in[0];
    const int*   edge_row = (const int*)d_in[1];
    const int*   edge_col = (const int*)d_in[2];
    const float* edge_val = (const float*)d_in[3];
    const float* W1       = (const float*)d_in[4];
    const float* W2       = (const float*)d_in[5];
    float*       out      = (float*)d_out;

    float *pH1, *pH2, *pH3;
    __nv_bfloat16 *pW1Th, *pW1Tl, *pW2Th, *pW2Tl;
    int *pRowptr;
    cudaGetSymbolAddress((void**)&pH1, g_H1);
    cudaGetSymbolAddress((void**)&pH2, g_H2);
    cudaGetSymbolAddress((void**)&pH3, g_H3);
    cudaGetSymbolAddress((void**)&pW1Th, g_W1Th);
    cudaGetSymbolAddress((void**)&pW1Tl, g_W1Tl);
    cudaGetSymbolAddress((void**)&pW2Th, g_W2Th);
    cudaGetSymbolAddress((void**)&pW2Tl, g_W2Tl);
    cudaGetSymbolAddress((void**)&pRowptr, g_rowptr);

    // ---- CSR build (counting sort by row) ----
    k_zero_int<<<(N_NODES + 1 + 255) / 256, 256>>>(pRowptr, N_NODES + 1);
    k_hist<<<(N_EDGES + 255) / 256, 256>>>(edge_row, N_EDGES);
    k_scan<<<1, 1024>>>(N_NODES + 1);
    k_scatter<<<(N_EDGES + 255) / 256, 256>>>(edge_row, edge_col, edge_val, N_EDGES);

    // ---- weight transpose + bf16 split ----
    k_tsplit<<<(D_IN * D_HID + 255) / 256, 256>>>(W1, pW1Th, pW1Tl, D_IN, D_HID);
    k_tsplit<<<(D_HID * D_OUT + 255) / 256, 256>>>(W2, pW2Th, pW2Tl, D_HID, D_OUT);

    int gridM = (N_NODES + 127) / 128;  // 391

    // ---- layer 1: H1 = Y @ W1 (HMMA, 3-term bf16 split) ----
    k_gemm_mma<<<dim3(D_HID / 128, gridM), 256>>>(Y, pW1Th, pW1Tl, pH1, N_NODES, D_HID);

    // ---- H2 = relu(spmm(H1)) ----
    {
        dim3 blk(D_HID / 4, 4);
        k_spmm4<D_HID, true><<<(N_NODES + 3) / 4, blk>>>(pH1, pH2);
    }

    // ---- layer 2: H3 = H2 @ W2 ----
    k_gemm_mma<<<dim3(D_OUT / 128, gridM), 256>>>(pH2, pW2Th, pW2Tl, pH3, N_NODES, D_OUT);

    // ---- out = spmm(H3) ----
    {
        dim3 blk(D_OUT / 4, 8);
        k_spmm4<D_OUT, false><<<(N_NODES + 7) / 8, blk>>>(pH3, out);
    }
}

// round 5
// speedup vs baseline: 2.6044x; 1.2704x over previous
#include <cuda_runtime.h>
#include <cuda_bf16.h>
#include <cstdint>

#define N_NODES 50000
#define N_EDGES 800000
#define D_IN    256
#define D_HID   256
#define D_OUT   128

// ---------------- scratch (static device globals; no allocation) -------------
__device__ float g_H1[(size_t)N_NODES * D_HID];
__device__ float g_H2[(size_t)N_NODES * D_HID];
__device__ float g_H3[(size_t)N_NODES * D_OUT];
__device__ __nv_bfloat16 g_W1Th[D_HID * D_IN];
__device__ __nv_bfloat16 g_W1Tl[D_HID * D_IN];
__device__ __nv_bfloat16 g_W2Th[D_OUT * D_HID];
__device__ __nv_bfloat16 g_W2Tl[D_OUT * D_HID];
__device__ int   g_rowptr[N_NODES + 1];
__device__ int   g_cursor[N_NODES];
__device__ int   g_bsum[256];
__device__ int2  g_ecv[N_EDGES];   // packed {col, val_bits}

// ---------------- K1: zero rowptr + transpose/split W1, W2 -------------------
__global__ void k_init(const float* __restrict__ W1, const float* __restrict__ W2) {
    int i = blockIdx.x * blockDim.x + threadIdx.x;
    if (i < N_NODES + 1) { g_rowptr[i] = 0; return; }
    i -= N_NODES + 1;
    if (i < D_IN * D_HID) {
        int r = i / D_HID, c = i % D_HID;
        float v = W1[i];
        __nv_bfloat16 h = __float2bfloat16(v);
        g_W1Th[(size_t)c * D_IN + r] = h;
        g_W1Tl[(size_t)c * D_IN + r] = __float2bfloat16(v - __bfloat162float(h));
        return;
    }
    i -= D_IN * D_HID;
    if (i < D_HID * D_OUT) {
        int r = i / D_OUT, c = i % D_OUT;
        float v = W2[i];
        __nv_bfloat16 h = __float2bfloat16(v);
        g_W2Th[(size_t)c * D_HID + r] = h;
        g_W2Tl[(size_t)c * D_HID + r] = __float2bfloat16(v - __bfloat162float(h));
    }
}

__global__ void k_hist(const int* __restrict__ row, int E) {
    int i = blockIdx.x * blockDim.x + threadIdx.x;
    if (i < E) atomicAdd(&g_rowptr[row[i] + 1], 1);
}

// ---------------- parallel scan: 3 phases ------------------------------------
__global__ void k_scan1() {   // 196 blocks x 256: in-place block-local inclusive scan
    __shared__ int sh[256];
    int t = threadIdx.x;
    int idx = blockIdx.x * 256 + t;
    int v = (idx < N_NODES + 1) ? g_rowptr[idx] : 0;
    sh[t] = v;
    __syncthreads();
#pragma unroll
    for (int off = 1; off < 256; off <<= 1) {
        int u = (t >= off) ? sh[t - off] : 0;
        __syncthreads();
        sh[t] += u;
        __syncthreads();
    }
    if (idx < N_NODES + 1) g_rowptr[idx] = sh[t];
    if (t == 255) g_bsum[blockIdx.x] = sh[255];
}

__global__ void k_scan2() {   // 1 block x 256: exclusive scan of block sums
    __shared__ int sh[256];
    int t = threadIdx.x;
    int v = (t < 196) ? g_bsum[t] : 0;
    sh[t] = v;
    __syncthreads();
#pragma unroll
    for (int off = 1; off < 256; off <<= 1) {
        int u = (t >= off) ? sh[t - off] : 0;
        __syncthreads();
        sh[t] += u;
        __syncthreads();
    }
    g_bsum[t] = sh[t] - v;
}

__global__ void k_scan3() {   // 196 blocks x 256: add offsets; write cursor
    int idx = blockIdx.x * 256 + threadIdx.x;
    if (idx < N_NODES + 1) {
        int v = g_rowptr[idx] + g_bsum[blockIdx.x];
        g_rowptr[idx] = v;
        if (idx < N_NODES) g_cursor[idx] = v;
    }
}

// ---------------- HMMA GEMM body (ldmatrix fragments) ------------------------
__device__ __forceinline__ void mma_bf16(float* c, const uint32_t* a, const uint32_t* b) {
    asm("mma.sync.aligned.m16n8k16.row.col.f32.bf16.bf16.f32 "
        "{%0,%1,%2,%3}, {%4,%5,%6,%7}, {%8,%9}, {%0,%1,%2,%3};"
        : "+f"(c[0]), "+f"(c[1]), "+f"(c[2]), "+f"(c[3])
        : "r"(a[0]), "r"(a[1]), "r"(a[2]), "r"(a[3]), "r"(b[0]), "r"(b[1]));
}

#define LDSM4(r0, r1, r2, r3, addr)                                            \
    asm volatile("ldmatrix.sync.aligned.m8n8.x4.shared.b16 {%0,%1,%2,%3}, [%4];" \
                 : "=r"(r0), "=r"(r1), "=r"(r2), "=r"(r3) : "r"(addr))

__device__ __forceinline__ void gemm_body(
    const float* __restrict__ A, const __nv_bfloat16* __restrict__ Bh,
    const __nv_bfloat16* __restrict__ Bl, float* __restrict__ C,
    int M, int N, int bx, int by)
{
    const int K = 256;
    const int SP = 40;   // row stride (80 B): ldmatrix 8-row phase hits all 32 banks once
    __shared__ __nv_bfloat16 sAh[128][SP];
    __shared__ __nv_bfloat16 sAl[128][SP];
    __shared__ __nv_bfloat16 sBh[128][SP];
    __shared__ __nv_bfloat16 sBl[128][SP];

    int tid = threadIdx.x;
    int lane = tid & 31, wid = tid >> 5;
    int rowBase = by * 128, colBase = bx * 128;
    int wm = (wid >> 2) * 64;
    int wn = (wid & 3) * 32;

    float acc[4][4][4];
#pragma unroll
    for (int mi = 0; mi < 4; mi++)
#pragma unroll
        for (int ni = 0; ni < 4; ni++)
#pragma unroll
            for (int q = 0; q < 4; q++) acc[mi][ni][q] = 0.f;

    uint32_t aHiB = (uint32_t)__cvta_generic_to_shared(&sAh[0][0]);
    uint32_t aLoB = (uint32_t)__cvta_generic_to_shared(&sAl[0][0]);
    uint32_t bHiB = (uint32_t)__cvta_generic_to_shared(&sBh[0][0]);
    uint32_t bLoB = (uint32_t)__cvta_generic_to_shared(&sBl[0][0]);

    // ldmatrix per-lane byte offsets
    uint32_t aOff[4], bOff[2];
    {
        int ra = ((lane & 8) ? 8 : 0) + (lane & 7);
        int ca = (lane & 16) ? 8 : 0;
#pragma unroll
        for (int mi = 0; mi < 4; mi++)
            aOff[mi] = (uint32_t)(((wm + mi * 16 + ra) * SP + ca) * 2);
        int rb = (lane & 7) + ((lane & 16) ? 8 : 0);
        int cb = (lane & 8) ? 8 : 0;
#pragma unroll
        for (int p = 0; p < 2; p++)
            bOff[p] = (uint32_t)(((wn + p * 16 + rb) * SP + cb) * 2);
    }

    for (int k0 = 0; k0 < K; k0 += 32) {
        // ---- A tile: load f32, split to bf16 hi/lo (128 rows x 32 k)
#pragma unroll
        for (int it = 0; it < 4; it++) {
            int ch = tid + it * 256;
            int r = ch >> 3, c = ch & 7;
            int gr = rowBase + r;
            float4 f = make_float4(0.f, 0.f, 0.f, 0.f);
            if (gr < M) f = *(const float4*)(A + (size_t)gr * K + k0 + c * 4);
            __nv_bfloat162 h01 = __floats2bfloat162_rn(f.x, f.y);
            __nv_bfloat162 h23 = __floats2bfloat162_rn(f.z, f.w);
            float2 g01 = __bfloat1622float2(h01);
            float2 g23 = __bfloat1622float2(h23);
            __nv_bfloat162 l01 = __floats2bfloat162_rn(f.x - g01.x, f.y - g01.y);
            __nv_bfloat162 l23 = __floats2bfloat162_rn(f.z - g23.x, f.w - g23.y);
            uint2 uh, ul;
            uh.x = *(uint32_t*)&h01; uh.y = *(uint32_t*)&h23;
            ul.x = *(uint32_t*)&l01; ul.y = *(uint32_t*)&l23;
            *(uint2*)&sAh[r][c * 4] = uh;
            *(uint2*)&sAl[r][c * 4] = ul;
        }
        // ---- B tile: copy pre-split bf16 (128 n x 32 k)
#pragma unroll
        for (int it = 0; it < 2; it++) {
            int ch = tid + it * 256;
            int r = ch >> 2, c = ch & 3;
            int gc = colBase + r;
            uint4 vh = *(const uint4*)(Bh + (size_t)gc * K + k0 + c * 8);
            uint4 vl = *(const uint4*)(Bl + (size_t)gc * K + k0 + c * 8);
            *(uint4*)&sBh[r][c * 8] = vh;
            *(uint4*)&sBl[r][c * 8] = vl;
        }
        __syncthreads();

#pragma unroll
        for (int ks = 0; ks < 2; ks++) {
            uint32_t kb = (uint32_t)(ks * 32);
            uint32_t bhr[8], blr[8];
            LDSM4(bhr[0], bhr[1], bhr[2], bhr[3], bHiB + bOff[0] + kb);
            LDSM4(bhr[4], bhr[5], bhr[6], bhr[7], bHiB + bOff[1] + kb);
            LDSM4(blr[0], blr[1], blr[2], blr[3], bLoB + bOff[0] + kb);
            LDSM4(blr[4], blr[5], blr[6], blr[7], bLoB + bOff[1] + kb);
#pragma unroll
            for (int mi = 0; mi < 4; mi++) {
                uint32_t ah[4], al[4];
                LDSM4(ah[0], ah[1], ah[2], ah[3], aHiB + aOff[mi] + kb);
                LDSM4(al[0], al[1], al[2], al[3], aLoB + aOff[mi] + kb);
#pragma unroll
                for (int ni = 0; ni < 4; ni++) {
                    mma_bf16(acc[mi][ni], ah, &bhr[ni * 2]);
                    mma_bf16(acc[mi][ni], ah, &blr[ni * 2]);
                    mma_bf16(acc[mi][ni], al, &bhr[ni * 2]);
                }
            }
        }
        __syncthreads();
    }

#pragma unroll
    for (int mi = 0; mi < 4; mi++) {
        int rr = rowBase + wm + mi * 16 + (lane >> 2);
#pragma unroll
        for (int ni = 0; ni < 4; ni++) {
            int cc = colBase + wn + ni * 8 + (lane & 3) * 2;
            if (rr < M)
                *(float2*)&C[(size_t)rr * N + cc] =
                    make_float2(acc[mi][ni][0], acc[mi][ni][1]);
            if (rr + 8 < M)
                *(float2*)&C[(size_t)(rr + 8) * N + cc] =
                    make_float2(acc[mi][ni][2], acc[mi][ni][3]);
        }
    }
}

// ---------------- fused: GEMM1 blocks + scatter blocks ------------------------
#define NG1 ((D_HID / 128) * ((N_NODES + 127) / 128))   // 782

__global__ __launch_bounds__(256, 2)
void k_gemm1_scatter(const float* __restrict__ A, float* __restrict__ C,
                     const int* __restrict__ erow, const int* __restrict__ ecol,
                     const float* __restrict__ eval)
{
    if (blockIdx.x < NG1) {
        gemm_body(A, g_W1Th, g_W1Tl, C, N_NODES, D_HID,
                  blockIdx.x & 1, blockIdx.x >> 1);
    } else {
        int i = (blockIdx.x - NG1) * 256 + threadIdx.x;
        if (i < N_EDGES) {
            int r = erow[i];
            int p = atomicAdd(&g_cursor[r], 1);
            g_ecv[p] = make_int2(ecol[i], __float_as_int(eval[i]));
        }
    }
}

__global__ __launch_bounds__(256, 2)
void k_gemm2(const float* __restrict__ A, float* __restrict__ C)
{
    gemm_body(A, g_W2Th, g_W2Tl, C, N_NODES, D_OUT, 0, blockIdx.x);
}

// ---------------- CSR SpMM ----------------------------------------------------
template <int F, bool RELU>
__global__ void k_spmm4(const float* __restrict__ X, float* __restrict__ Yout) {
    int r = blockIdx.x * blockDim.y + threadIdx.y;
    if (r >= N_NODES) return;
    int f4 = threadIdx.x;
    int e   = g_rowptr[r];
    int end = g_rowptr[r + 1];
    float4 acc = make_float4(0.f, 0.f, 0.f, 0.f);
    for (; e < end; e++) {
        int2 cv = __ldg(&g_ecv[e]);
        float v = __int_as_float(cv.y);
        float4 x = *(const float4*)&X[(size_t)cv.x * F + f4 * 4];
        acc.x += v * x.x;
        acc.y += v * x.y;
        acc.z += v * x.z;
        acc.w += v * x.w;
    }
    if (RELU) {
        acc.x = fmaxf(acc.x, 0.f);
        acc.y = fmaxf(acc.y, 0.f);
        acc.z = fmaxf(acc.z, 0.f);
        acc.w = fmaxf(acc.w, 0.f);
    }
    *(float4*)&Yout[(size_t)r * F + f4 * 4] = acc;
}

// ---------------- launch ------------------------------------------------------
extern "C" void kernel_launch(void* const* d_in, const int* in_sizes, int n_in,
                              void* d_out, int out_size) {
    const float* Y        = (const float*)d_in[0];
    const int*   edge_row = (const int*)d_in[1];
    const int*   edge_col = (const int*)d_in[2];
    const float* edge_val = (const float*)d_in[3];
    const float* W1       = (const float*)d_in[4];
    const float* W2       = (const float*)d_in[5];
    float*       out      = (float*)d_out;

    float *pH1, *pH2, *pH3;
    cudaGetSymbolAddress((void**)&pH1, g_H1);
    cudaGetSymbolAddress((void**)&pH2, g_H2);
    cudaGetSymbolAddress((void**)&pH3, g_H3);

    // K1: zero rowptr + W transposes/splits
    {
        int total = (N_NODES + 1) + D_IN * D_HID + D_HID * D_OUT;
        k_init<<<(total + 255) / 256, 256>>>(W1, W2);
    }
    // K2: histogram
    k_hist<<<(N_EDGES + 255) / 256, 256>>>(edge_row, N_EDGES);
    // K3-5: parallel scan (+ cursor)
    k_scan1<<<196, 256>>>();
    k_scan2<<<1, 256>>>();
    k_scan3<<<196, 256>>>();
    // K6: GEMM1 fused with edge scatter (independent work, one launch)
    k_gemm1_scatter<<<NG1 + (N_EDGES + 255) / 256, 256>>>(Y, pH1, edge_row, edge_col, edge_val);
    // K7: H2 = relu(spmm(H1))
    {
        dim3 blk(D_HID / 4, 4);
        k_spmm4<D_HID, true><<<(N_NODES + 3) / 4, blk>>>(pH1, pH2);
    }
    // K8: H3 = H2 @ W2
    k_gemm2<<<(N_NODES + 127) / 128, 256>>>(pH2, pH3);
    // K9: out = spmm(H3)
    {
        dim3 blk(D_OUT / 4, 8);
        k_spmm4<D_OUT, false><<<(N_NODES + 7) / 8, blk>>>(pH3, out);
    }
}